// round 16
// baseline (speedup 1.0000x reference)
#include <cuda_runtime.h>
#include <cuda_fp16.h>
#include <cstdint>

// ---------------------------------------------------------------------------
// GQA: B=4, S=2048, E=1024, H=16, G=4, HPG=4, HD=64, KV_DIM=256
// Round 16: latency-hiding pass on the fp16 kernels.
//   - GEMM: warp tile 64x32, block 128x128, __launch_bounds__(256,2)
//     -> 2 CTAs/SM, 16 warps/SM (was 8, issue-starved at 15%).
//   - Attention: register-prefetch of next K/V tile (LDG issued during
//     current tile's compute; only STS on the critical path).
// ---------------------------------------------------------------------------

#define B_   4
#define S_   2048
#define E_   1024
#define G_   4
#define HD_  64
#define KV_  256
#define M_   (B_ * S_)

__device__ float g_Q[(size_t)M_ * E_];
__device__ float g_K[(size_t)M_ * KV_];
__device__ float g_V[(size_t)M_ * KV_];
__device__ float g_A[(size_t)M_ * E_];

__device__ __forceinline__ unsigned f2h2(float a, float b) {
    __half2 h = __floats2half2_rn(a, b);
    return *reinterpret_cast<unsigned*>(&h);
}

__device__ __forceinline__ void mma_f16(float* c, const unsigned* a, const unsigned* b) {
    asm volatile(
        "mma.sync.aligned.m16n8k16.row.col.f32.f16.f16.f32 "
        "{%0,%1,%2,%3}, {%4,%5,%6,%7}, {%8,%9}, {%0,%1,%2,%3};\n"
        : "+f"(c[0]), "+f"(c[1]), "+f"(c[2]), "+f"(c[3])
        : "r"(a[0]), "r"(a[1]), "r"(a[2]), "r"(a[3]),
          "r"(b[0]), "r"(b[1]));
}

// ---------------------------------------------------------------------------
// fp16 GEMM: C[M,N] = A[M,K] @ W[K,N] + bias[N]
// Block 128x128, BK=32, 256 threads = 8 warps (2m x 4n), warp tile 64x32.
// As [128][20] words (half2 packs k-pairs; frag banks 20*gid+tg distinct).
// Bs [16][136] words (word(kw,n)=half2{W[2kw][n],W[2kw+1][n]}; 136 ≡ 8 mod 32
// -> frag banks 8*tg+gid distinct; fill col=(tid&15)*4 (+64) STS.128 covers
// all 32 banks). 2 CTAs/SM. Requires M%128==0, N%128==0, K%32==0.
// ---------------------------------------------------------------------------
#define ASTR 20
#define BSTR 136

__device__ __forceinline__ void gemm_body(
    const float* __restrict__ A, const float* __restrict__ W,
    const float* __restrict__ bias, float* __restrict__ C,
    int M, int N, int K, int bx, int by)
{
    __shared__ unsigned As[128][ASTR];   // 10240 B
    __shared__ unsigned Bs[16][BSTR];    //  8704 B

    const int tid  = threadIdx.x;
    const int lane = tid & 31;
    const int warp = tid >> 5;
    const int gid  = lane >> 2;
    const int tg   = lane & 3;
    const int wm0  = (warp >> 2) * 64;
    const int wn0  = (warp & 3) * 32;
    const int row0 = by * 128;
    const int col0 = bx * 128;

    // A fill: 128 rows x 16 words / 256 thr
    const int arow = tid >> 1;
    const int akw0 = (tid & 1) * 8;
    // B fill: 16 kwords x 128 words / 256 thr = 8 words (2 x uint4)
    const int bkw = tid >> 4;            // 0..15
    const int bnb = (tid & 15) * 4;      // word col 0..60 (+64 for 2nd store)

    const float* Abase = A + (size_t)(row0 + arow) * K + (tid & 1) * 16;
    const float* Wb0   = W + (size_t)(2 * bkw)     * N + col0;
    const float* Wb1   = W + (size_t)(2 * bkw + 1) * N + col0;

    float4 pa[4], pba[2], pbb[2];

#pragma unroll
    for (int i = 0; i < 4; i++) pa[i] = *(const float4*)(Abase + i * 4);
#pragma unroll
    for (int s = 0; s < 2; s++) {
        pba[s] = *(const float4*)(Wb0 + bnb + 64 * s);
        pbb[s] = *(const float4*)(Wb1 + bnb + 64 * s);
    }

#pragma unroll
    for (int i = 0; i < 4; i++) {
        uint2 t;
        t.x = f2h2(pa[i].x, pa[i].y);
        t.y = f2h2(pa[i].z, pa[i].w);
        *(uint2*)&As[arow][akw0 + 2 * i] = t;
    }
#pragma unroll
    for (int s = 0; s < 2; s++) {
        uint4 t;
        t.x = f2h2(pba[s].x, pbb[s].x);
        t.y = f2h2(pba[s].y, pbb[s].y);
        t.z = f2h2(pba[s].z, pbb[s].z);
        t.w = f2h2(pba[s].w, pbb[s].w);
        *(uint4*)&Bs[bkw][bnb + 64 * s] = t;
    }
    __syncthreads();

    float acc[4][4][4];
#pragma unroll
    for (int mt = 0; mt < 4; mt++)
#pragma unroll
        for (int nt = 0; nt < 4; nt++)
#pragma unroll
            for (int r = 0; r < 4; r++) acc[mt][nt][r] = 0.0f;

    for (int k0 = 0; k0 < K; k0 += 32) {
        const bool has_next = (k0 + 32) < K;
        if (has_next) {
#pragma unroll
            for (int i = 0; i < 4; i++)
                pa[i] = *(const float4*)(Abase + (k0 + 32) + i * 4);
#pragma unroll
            for (int s = 0; s < 2; s++) {
                pba[s] = *(const float4*)(Wb0 + (size_t)(k0 + 32) * N + bnb + 64 * s);
                pbb[s] = *(const float4*)(Wb1 + (size_t)(k0 + 32) * N + bnb + 64 * s);
            }
        }

#pragma unroll
        for (int ks = 0; ks < 2; ks++) {
            unsigned a[4][4];
            unsigned b[4][2];
#pragma unroll
            for (int mt = 0; mt < 4; mt++) {
                int m = wm0 + mt * 16 + gid;
                a[mt][0] = As[m][ks * 8 + tg];
                a[mt][1] = As[m + 8][ks * 8 + tg];
                a[mt][2] = As[m][ks * 8 + tg + 4];
                a[mt][3] = As[m + 8][ks * 8 + tg + 4];
            }
#pragma unroll
            for (int nt = 0; nt < 4; nt++) {
                b[nt][0] = Bs[ks * 8 + tg][wn0 + nt * 8 + gid];
                b[nt][1] = Bs[ks * 8 + tg + 4][wn0 + nt * 8 + gid];
            }
#pragma unroll
            for (int mt = 0; mt < 4; mt++)
#pragma unroll
                for (int nt = 0; nt < 4; nt++)
                    mma_f16(acc[mt][nt], a[mt], b[nt]);
        }
        __syncthreads();

        if (has_next) {
#pragma unroll
            for (int i = 0; i < 4; i++) {
                uint2 t;
                t.x = f2h2(pa[i].x, pa[i].y);
                t.y = f2h2(pa[i].z, pa[i].w);
                *(uint2*)&As[arow][akw0 + 2 * i] = t;
            }
#pragma unroll
            for (int s = 0; s < 2; s++) {
                uint4 t;
                t.x = f2h2(pba[s].x, pbb[s].x);
                t.y = f2h2(pba[s].y, pbb[s].y);
                t.z = f2h2(pba[s].z, pbb[s].z);
                t.w = f2h2(pba[s].w, pbb[s].w);
                *(uint4*)&Bs[bkw][bnb + 64 * s] = t;
            }
            __syncthreads();
        }
    }

#pragma unroll
    for (int mt = 0; mt < 4; mt++) {
        int r0 = row0 + wm0 + mt * 16 + gid;
#pragma unroll
        for (int nt = 0; nt < 4; nt++) {
            int c = col0 + wn0 + nt * 8 + 2 * tg;
            float bx0 = bias[c], by0 = bias[c + 1];
            float2 v0 = make_float2(acc[mt][nt][0] + bx0, acc[mt][nt][1] + by0);
            float2 v1 = make_float2(acc[mt][nt][2] + bx0, acc[mt][nt][3] + by0);
            *(float2*)&C[(size_t)r0 * N + c]       = v0;
            *(float2*)&C[(size_t)(r0 + 8) * N + c] = v1;
        }
    }
}

__global__ __launch_bounds__(256, 2) void gemm_f16(
    const float* __restrict__ A, const float* __restrict__ W,
    const float* __restrict__ bias, float* __restrict__ C,
    int M, int N, int K)
{
    gemm_body(A, W, bias, C, M, N, K, blockIdx.x, blockIdx.y);
}

// Fused K+V projection: 2 col-tiles per matrix; x<2 -> K, x>=2 -> V.
__global__ __launch_bounds__(256, 2) void gemm_kv_f16(
    const float* __restrict__ A,
    const float* __restrict__ Wk, const float* __restrict__ bk, float* __restrict__ Kp,
    const float* __restrict__ Wv, const float* __restrict__ bv, float* __restrict__ Vp)
{
    const bool is_v = (blockIdx.x >= 2);
    gemm_body(A,
              is_v ? Wv : Wk,
              is_v ? bv : bk,
              is_v ? Vp : Kp,
              M_, KV_, E_,
              is_v ? (int)blockIdx.x - 2 : (int)blockIdx.x,
              blockIdx.y);
}

// ---------------------------------------------------------------------------
// Flash attention, fp16 mma, fixed-shift softmax (exp2f), K/V REGISTER
// PREFETCH: LDGs for tile t+1 are issued right after tile t's STS barrier,
// consumed (converted+stored) at the next boundary -> LDG latency hidden
// behind the S/softmax/PV compute. 128 threads (4 warps), 128 q-rows/CTA,
// 64-key tiles, 2 CTAs/SM. Layouts as R15 (Qs/Ks half2-d, Vsp key-pair,
// Ps half2-key). Grid: (S/128, B*16). Output: col = p*256 + grp*64 + d.
// ---------------------------------------------------------------------------
#define QROWS 128
#define NTHR  128
#define QSTR  36
#define KSTR  36
#define VSTR  72
#define QSCALE 0.18033688011112042f   // 0.125 * log2(e)

__global__ __launch_bounds__(NTHR) void attn_f16(
    const float* __restrict__ Qg, const float* __restrict__ Kg,
    const float* __restrict__ Vg, float* __restrict__ Ag)
{
    extern __shared__ unsigned smx[];
    unsigned (*Qs)[QSTR]  = (unsigned(*)[QSTR])(smx);                                // [q][dw]
    unsigned (*Ks)[KSTR]  = (unsigned(*)[KSTR])(smx + QROWS * QSTR);                 // [key][dw]
    unsigned (*Vsp)[VSTR] = (unsigned(*)[VSTR])(smx + QROWS * QSTR + 64 * KSTR);     // [kw][d]
    unsigned (*Ps)[QSTR]  = (unsigned(*)[QSTR])(smx + QROWS * QSTR + 64 * KSTR + 32 * VSTR); // [q][kw]

    const int tid  = threadIdx.x;
    const int lane = tid & 31;
    const int warp = tid >> 5;
    const int gid  = lane >> 2;
    const int tg   = lane & 3;
    const int wq0  = warp * 32;

    const int q0   = blockIdx.x * QROWS;
    const int head = blockIdx.y;
    const int b    = head >> 4;
    const int grp  = (head >> 2) & 3;
    const int p    = head & 3;
    const int h    = grp * 4 + p;

    const float* Kbase = Kg + (size_t)(b * S_) * KV_ + grp * HD_;
    const float* Vbase = Vg + (size_t)(b * S_) * KV_ + grp * HD_;

    // Per-thread fill coordinates
    const int kc = tid >> 4;             // K row handled in iteration i: kc + 8i? no:
    // K: idx = tid + 128*i -> c = idx>>4 = (tid>>4) + 8*i, dw = (tid&15)*2
    const int kdw = (tid & 15) * 2;
    // V: idx = tid + 128*i (i<4) -> kw = (tid>>4) + 8*i, d = (tid&15)*4
    const int vd = (tid & 15) * 4;

    float4 kst[8];     // K staging: rows kc+8i, 4 floats each
    float4 vsa[4], vsb[4];  // V staging: key rows 2kw, 2kw+1

    auto ldg_tile = [&](int kv0) {
#pragma unroll
        for (int i = 0; i < 8; i++) {
            int c = kc + 8 * i;
            kst[i] = *(const float4*)(Kbase + (size_t)(kv0 + c) * KV_ + kdw * 2);
        }
#pragma unroll
        for (int i = 0; i < 4; i++) {
            int kw = kc + 8 * i;
            size_t base = (size_t)(kv0 + 2 * kw) * KV_ + vd;
            vsa[i] = *(const float4*)(Vbase + base);
            vsb[i] = *(const float4*)(Vbase + base + KV_);
        }
    };
    auto sts_tile = [&]() {
#pragma unroll
        for (int i = 0; i < 8; i++) {
            int c = kc + 8 * i;
            uint2 t;
            t.x = f2h2(kst[i].x, kst[i].y);
            t.y = f2h2(kst[i].z, kst[i].w);
            *(uint2*)&Ks[c][kdw] = t;
        }
#pragma unroll
        for (int i = 0; i < 4; i++) {
            int kw = kc + 8 * i;
            uint4 t;
            t.x = f2h2(vsa[i].x, vsb[i].x);
            t.y = f2h2(vsa[i].y, vsb[i].y);
            t.z = f2h2(vsa[i].z, vsb[i].z);
            t.w = f2h2(vsa[i].w, vsb[i].w);
            *(uint4*)&Vsp[kw][vd] = t;
        }
    };

    // Load Q tile (scaled, packed half2) + prefetch first K/V tile.
#pragma unroll
    for (int i = 0; i < 16; i++) {
        int idx = tid + NTHR * i;
        int r = idx >> 4;
        int dw = (idx & 15) * 2;
        float4 v = *(const float4*)(Qg + (size_t)(b * S_ + q0 + r) * E_ + h * HD_ + dw * 2);
        uint2 t;
        t.x = f2h2(v.x * QSCALE, v.y * QSCALE);
        t.y = f2h2(v.z * QSCALE, v.w * QSCALE);
        *(uint2*)&Qs[r][dw] = t;
    }
    ldg_tile(0);

    float oacc[2][8][4];
#pragma unroll
    for (int mt = 0; mt < 2; mt++)
#pragma unroll
        for (int nt = 0; nt < 8; nt++)
#pragma unroll
            for (int r = 0; r < 4; r++) oacc[mt][nt][r] = 0.0f;

    float lrow[2][2];
#pragma unroll
    for (int mt = 0; mt < 2; mt++) { lrow[mt][0] = 0.0f; lrow[mt][1] = 0.0f; }

    const int NTILE = S_ / 64;
    for (int t = 0; t < NTILE; t++) {
        __syncthreads();     // consumers of tile t-1 done with Ks/Vsp
        sts_tile();
        __syncthreads();     // tile t visible to all warps
        if (t + 1 < NTILE) ldg_tile((t + 1) * 64);   // hidden behind compute

        // ---- S = Q @ K^T : warp tile 32 x 64 (k = d, 4 steps of k16) ----
        float sacc[2][8][4];
#pragma unroll
        for (int mt = 0; mt < 2; mt++)
#pragma unroll
            for (int nt = 0; nt < 8; nt++)
#pragma unroll
                for (int r = 0; r < 4; r++) sacc[mt][nt][r] = 0.0f;

#pragma unroll
        for (int ks = 0; ks < 4; ks++) {
            unsigned a[2][4];
#pragma unroll
            for (int mt = 0; mt < 2; mt++) {
                int row = wq0 + mt * 16 + gid;
                a[mt][0] = Qs[row][ks * 8 + tg];
                a[mt][1] = Qs[row + 8][ks * 8 + tg];
                a[mt][2] = Qs[row][ks * 8 + tg + 4];
                a[mt][3] = Qs[row + 8][ks * 8 + tg + 4];
            }
            unsigned bb[8][2];
#pragma unroll
            for (int nt = 0; nt < 8; nt++) {
                bb[nt][0] = Ks[nt * 8 + gid][ks * 8 + tg];
                bb[nt][1] = Ks[nt * 8 + gid][ks * 8 + tg + 4];
            }
#pragma unroll
            for (int mt = 0; mt < 2; mt++)
#pragma unroll
                for (int nt = 0; nt < 8; nt++)
                    mma_f16(sacc[mt][nt], a[mt], bb[nt]);
        }

        // ---- fixed-shift softmax: e = exp2(s'); pack adjacent-key pairs ----
#pragma unroll
        for (int mt = 0; mt < 2; mt++) {
            int r1 = wq0 + mt * 16 + gid;
            float sum0 = lrow[mt][0], sum1 = lrow[mt][1];
#pragma unroll
            for (int nt = 0; nt < 8; nt++) {
                float e0 = exp2f(sacc[mt][nt][0]);
                float e1 = exp2f(sacc[mt][nt][1]);
                float e2 = exp2f(sacc[mt][nt][2]);
                float e3 = exp2f(sacc[mt][nt][3]);
                sum0 += e0 + e1;
                sum1 += e2 + e3;
                Ps[r1][nt * 4 + tg]     = f2h2(e0, e1);
                Ps[r1 + 8][nt * 4 + tg] = f2h2(e2, e3);
            }
            lrow[mt][0] = sum0;
            lrow[mt][1] = sum1;
        }

        __syncwarp();   // Ps rows are warp-private

        // ---- O += P @ V : warp tile 32 x 64 (k = key, 4 steps of k16) ----
#pragma unroll
        for (int ks = 0; ks < 4; ks++) {
            unsigned a[2][4];
#pragma unroll
            for (int mt = 0; mt < 2; mt++) {
                int row = wq0 + mt * 16 + gid;
                a[mt][0] = Ps[row][ks * 8 + tg];
                a[mt][1] = Ps[row + 8][ks * 8 + tg];
                a[mt][2] = Ps[row][ks * 8 + tg + 4];
                a[mt][3] = Ps[row + 8][ks * 8 + tg + 4];
            }
            unsigned bb[8][2];
#pragma unroll
            for (int nt = 0; nt < 8; nt++) {
                bb[nt][0] = Vsp[ks * 8 + tg][nt * 8 + gid];
                bb[nt][1] = Vsp[ks * 8 + tg + 4][nt * 8 + gid];
            }
#pragma unroll
            for (int mt = 0; mt < 2; mt++)
#pragma unroll
                for (int nt = 0; nt < 8; nt++)
                    mma_f16(oacc[mt][nt], a[mt], bb[nt]);
        }
    }

    // Deferred row-sum reduction (4 lanes per row share the sum).
#pragma unroll
    for (int mt = 0; mt < 2; mt++) {
#pragma unroll
        for (int j = 0; j < 2; j++) {
            lrow[mt][j] += __shfl_xor_sync(0xffffffffu, lrow[mt][j], 1);
            lrow[mt][j] += __shfl_xor_sync(0xffffffffu, lrow[mt][j], 2);
        }
    }

    // Normalize + store permuted: col = p*256 + grp*64 + d
    const int cbase = p * (G_ * HD_) + grp * HD_;
#pragma unroll
    for (int mt = 0; mt < 2; mt++) {
        float inv0 = 1.0f / lrow[mt][0];
        float inv1 = 1.0f / lrow[mt][1];
        int r0 = b * S_ + q0 + wq0 + mt * 16 + gid;
#pragma unroll
        for (int nt = 0; nt < 8; nt++) {
            int c = cbase + nt * 8 + 2 * tg;
            float2 v0 = make_float2(oacc[mt][nt][0] * inv0, oacc[mt][nt][1] * inv0);
            float2 v1 = make_float2(oacc[mt][nt][2] * inv1, oacc[mt][nt][3] * inv1);
            *(float2*)&Ag[(size_t)r0 * E_ + c]       = v0;
            *(float2*)&Ag[(size_t)(r0 + 8) * E_ + c] = v1;
        }
    }
}

// ---------------------------------------------------------------------------
// Launch
// ---------------------------------------------------------------------------
extern "C" void kernel_launch(void* const* d_in, const int* in_sizes, int n_in,
                              void* d_out, int out_size)
{
    const float* x  = (const float*)d_in[0];
    const float* Wq = (const float*)d_in[1];
    const float* bq = (const float*)d_in[2];
    const float* Wk = (const float*)d_in[3];
    const float* bk = (const float*)d_in[4];
    const float* Wv = (const float*)d_in[5];
    const float* bv = (const float*)d_in[6];
    const float* Wo = (const float*)d_in[7];
    const float* bo = (const float*)d_in[8];
    float* out = (float*)d_out;

    float *Qp, *Kp, *Vp, *Ap;
    cudaGetSymbolAddress((void**)&Qp, g_Q);
    cudaGetSymbolAddress((void**)&Kp, g_K);
    cudaGetSymbolAddress((void**)&Vp, g_V);
    cudaGetSymbolAddress((void**)&Ap, g_A);

    const int smem_attn =
        (QROWS * QSTR + 64 * KSTR + 32 * VSTR + QROWS * QSTR) * (int)sizeof(unsigned); // 55296
    cudaFuncSetAttribute((const void*)attn_f16,
                         cudaFuncAttributeMaxDynamicSharedMemorySize, smem_attn);

    // Q projection (block tile 128x128)
    gemm_f16<<<dim3(E_ / 128, M_ / 128), 256>>>(x, Wq, bq, Qp, M_, E_, E_);
    // K + V projections fused
    gemm_kv_f16<<<dim3(4, M_ / 128), 256>>>(x, Wk, bk, Kp, Wv, bv, Vp);
    // Attention (permuted output)
    attn_f16<<<dim3(S_ / QROWS, B_ * 16), NTHR, smem_attn>>>(Qp, Kp, Vp, Ap);
    // Output projection
    gemm_f16<<<dim3(E_ / 128, M_ / 128), 256>>>(Ap, Wo, bo, out, M_, E_, E_);
}

// round 17
// speedup vs baseline: 1.1282x; 1.1282x over previous
#include <cuda_runtime.h>
#include <cuda_fp16.h>
#include <cstdint>

// ---------------------------------------------------------------------------
// GQA: B=4, S=2048, E=1024, H=16, G=4, HPG=4, HD=64, KV_DIM=256
// Round 17: recombination of measured-best halves:
//   - GEMM from R15: block 128x256, warp tile 64x64 (LDS:MMA 1:1), 8 warps
//   - Attention from R16: K/V register prefetch (LDG off the critical path)
// fp16 mma.m16n8k16 everywhere, fp32 accumulate, fixed-shift exp2 softmax.
// ---------------------------------------------------------------------------

#define B_   4
#define S_   2048
#define E_   1024
#define G_   4
#define HD_  64
#define KV_  256
#define M_   (B_ * S_)

__device__ float g_Q[(size_t)M_ * E_];
__device__ float g_K[(size_t)M_ * KV_];
__device__ float g_V[(size_t)M_ * KV_];
__device__ float g_A[(size_t)M_ * E_];

__device__ __forceinline__ unsigned f2h2(float a, float b) {
    __half2 h = __floats2half2_rn(a, b);
    return *reinterpret_cast<unsigned*>(&h);
}

__device__ __forceinline__ void mma_f16(float* c, const unsigned* a, const unsigned* b) {
    asm volatile(
        "mma.sync.aligned.m16n8k16.row.col.f32.f16.f16.f32 "
        "{%0,%1,%2,%3}, {%4,%5,%6,%7}, {%8,%9}, {%0,%1,%2,%3};\n"
        : "+f"(c[0]), "+f"(c[1]), "+f"(c[2]), "+f"(c[3])
        : "r"(a[0]), "r"(a[1]), "r"(a[2]), "r"(a[3]),
          "r"(b[0]), "r"(b[1]));
}

// ---------------------------------------------------------------------------
// fp16 GEMM (R15): C[M,N] = A[M,K] @ W[K,N] + bias[N]
// Block tile 128x256, BK=32, 256 threads = 8 warps (2m x 4n), warp tile 64x64.
// As  [128][20] words: half2 packs (k,k+1) along k.
// Bsp [16][264] words: word(kw, n) = half2{W[2kw][n], W[2kw+1][n]}.
// Static smem 27136 B. Requires M%128==0, N%256==0, K%32==0.
// ---------------------------------------------------------------------------
#define ASTR 20
#define BSTR 264

__device__ __forceinline__ void gemm_body(
    const float* __restrict__ A, const float* __restrict__ W,
    const float* __restrict__ bias, float* __restrict__ C,
    int M, int N, int K, int bx, int by)
{
    __shared__ unsigned As[128][ASTR];   // 10240 B
    __shared__ unsigned Bs[16][BSTR];    // 16896 B

    const int tid  = threadIdx.x;
    const int lane = tid & 31;
    const int warp = tid >> 5;
    const int gid  = lane >> 2;
    const int tg   = lane & 3;
    const int wm0  = (warp >> 2) * 64;
    const int wn0  = (warp & 3) * 64;
    const int row0 = by * 128;
    const int col0 = bx * 256;

    const int arow = tid >> 1;
    const int akw0 = (tid & 1) * 8;
    const int bkw = tid >> 4;                // 0..15
    const int bnb = (tid & 15) * 4;          // 0..60

    const float* Abase = A + (size_t)(row0 + arow) * K + (tid & 1) * 16;
    const float* Wb0   = W + (size_t)(2 * bkw)     * N + col0 + bnb;
    const float* Wb1   = W + (size_t)(2 * bkw + 1) * N + col0 + bnb;

    float4 pa[4], pba[4], pbb[4];

#pragma unroll
    for (int i = 0; i < 4; i++) pa[i] = *(const float4*)(Abase + i * 4);
#pragma unroll
    for (int s = 0; s < 4; s++) {
        pba[s] = *(const float4*)(Wb0 + 64 * s);
        pbb[s] = *(const float4*)(Wb1 + 64 * s);
    }

#pragma unroll
    for (int i = 0; i < 4; i++) {
        uint2 t;
        t.x = f2h2(pa[i].x, pa[i].y);
        t.y = f2h2(pa[i].z, pa[i].w);
        *(uint2*)&As[arow][akw0 + 2 * i] = t;
    }
#pragma unroll
    for (int s = 0; s < 4; s++) {
        uint4 t;
        t.x = f2h2(pba[s].x, pbb[s].x);
        t.y = f2h2(pba[s].y, pbb[s].y);
        t.z = f2h2(pba[s].z, pbb[s].z);
        t.w = f2h2(pba[s].w, pbb[s].w);
        *(uint4*)&Bs[bkw][bnb + 64 * s] = t;
    }
    __syncthreads();

    float acc[4][8][4];
#pragma unroll
    for (int mt = 0; mt < 4; mt++)
#pragma unroll
        for (int nt = 0; nt < 8; nt++)
#pragma unroll
            for (int r = 0; r < 4; r++) acc[mt][nt][r] = 0.0f;

    for (int k0 = 0; k0 < K; k0 += 32) {
        const bool has_next = (k0 + 32) < K;
        if (has_next) {
#pragma unroll
            for (int i = 0; i < 4; i++)
                pa[i] = *(const float4*)(Abase + (k0 + 32) + i * 4);
#pragma unroll
            for (int s = 0; s < 4; s++) {
                pba[s] = *(const float4*)(Wb0 + (size_t)(k0 + 32) * N + 64 * s);
                pbb[s] = *(const float4*)(Wb1 + (size_t)(k0 + 32) * N + 64 * s);
            }
        }

#pragma unroll
        for (int ks = 0; ks < 2; ks++) {
            unsigned a[4][4];
            unsigned b[8][2];
#pragma unroll
            for (int mt = 0; mt < 4; mt++) {
                int m = wm0 + mt * 16 + gid;
                a[mt][0] = As[m][ks * 8 + tg];
                a[mt][1] = As[m + 8][ks * 8 + tg];
                a[mt][2] = As[m][ks * 8 + tg + 4];
                a[mt][3] = As[m + 8][ks * 8 + tg + 4];
            }
#pragma unroll
            for (int nt = 0; nt < 8; nt++) {
                b[nt][0] = Bs[ks * 8 + tg][wn0 + nt * 8 + gid];
                b[nt][1] = Bs[ks * 8 + tg + 4][wn0 + nt * 8 + gid];
            }
#pragma unroll
            for (int mt = 0; mt < 4; mt++)
#pragma unroll
                for (int nt = 0; nt < 8; nt++)
                    mma_f16(acc[mt][nt], a[mt], b[nt]);
        }
        __syncthreads();

        if (has_next) {
#pragma unroll
            for (int i = 0; i < 4; i++) {
                uint2 t;
                t.x = f2h2(pa[i].x, pa[i].y);
                t.y = f2h2(pa[i].z, pa[i].w);
                *(uint2*)&As[arow][akw0 + 2 * i] = t;
            }
#pragma unroll
            for (int s = 0; s < 4; s++) {
                uint4 t;
                t.x = f2h2(pba[s].x, pbb[s].x);
                t.y = f2h2(pba[s].y, pbb[s].y);
                t.z = f2h2(pba[s].z, pbb[s].z);
                t.w = f2h2(pba[s].w, pbb[s].w);
                *(uint4*)&Bs[bkw][bnb + 64 * s] = t;
            }
            __syncthreads();
        }
    }

#pragma unroll
    for (int mt = 0; mt < 4; mt++) {
        int r0 = row0 + wm0 + mt * 16 + gid;
#pragma unroll
        for (int nt = 0; nt < 8; nt++) {
            int c = col0 + wn0 + nt * 8 + 2 * tg;
            float bx0 = bias[c], by0 = bias[c + 1];
            float2 v0 = make_float2(acc[mt][nt][0] + bx0, acc[mt][nt][1] + by0);
            float2 v1 = make_float2(acc[mt][nt][2] + bx0, acc[mt][nt][3] + by0);
            *(float2*)&C[(size_t)r0 * N + c]       = v0;
            *(float2*)&C[(size_t)(r0 + 8) * N + c] = v1;
        }
    }
}

__global__ __launch_bounds__(256, 1) void gemm_f16(
    const float* __restrict__ A, const float* __restrict__ W,
    const float* __restrict__ bias, float* __restrict__ C,
    int M, int N, int K)
{
    gemm_body(A, W, bias, C, M, N, K, blockIdx.x, blockIdx.y);
}

// Fused K+V projection (N=256 each): grid.x = 2, x=0 -> K, x=1 -> V.
__global__ __launch_bounds__(256, 1) void gemm_kv_f16(
    const float* __restrict__ A,
    const float* __restrict__ Wk, const float* __restrict__ bk, float* __restrict__ Kp,
    const float* __restrict__ Wv, const float* __restrict__ bv, float* __restrict__ Vp)
{
    const bool is_v = (blockIdx.x >= 1);
    gemm_body(A,
              is_v ? Wv : Wk,
              is_v ? bv : bk,
              is_v ? Vp : Kp,
              M_, KV_, E_,
              0, blockIdx.y);
}

// ---------------------------------------------------------------------------
// Flash attention (R16): fp16 mma, fixed-shift softmax (exp2f), K/V register
// prefetch. 128 threads (4 warps), 128 q-rows/CTA, 64-key tiles, 2 CTAs/SM.
// Qs [128][36] (half2 d-pairs), Ks [64][36], Vsp [32][72] (key-pair packed),
// Ps [128][36] (half2 key-pairs). Grid: (S/128, B*16).
// Output permuted: col = p*256 + grp*64 + d.
// ---------------------------------------------------------------------------
#define QROWS 128
#define NTHR  128
#define QSTR  36
#define KSTR  36
#define VSTR  72
#define QSCALE 0.18033688011112042f   // 0.125 * log2(e)

__global__ __launch_bounds__(NTHR) void attn_f16(
    const float* __restrict__ Qg, const float* __restrict__ Kg,
    const float* __restrict__ Vg, float* __restrict__ Ag)
{
    extern __shared__ unsigned smx[];
    unsigned (*Qs)[QSTR]  = (unsigned(*)[QSTR])(smx);                                // [q][dw]
    unsigned (*Ks)[KSTR]  = (unsigned(*)[KSTR])(smx + QROWS * QSTR);                 // [key][dw]
    unsigned (*Vsp)[VSTR] = (unsigned(*)[VSTR])(smx + QROWS * QSTR + 64 * KSTR);     // [kw][d]
    unsigned (*Ps)[QSTR]  = (unsigned(*)[QSTR])(smx + QROWS * QSTR + 64 * KSTR + 32 * VSTR); // [q][kw]

    const int tid  = threadIdx.x;
    const int lane = tid & 31;
    const int warp = tid >> 5;
    const int gid  = lane >> 2;
    const int tg   = lane & 3;
    const int wq0  = warp * 32;

    const int q0   = blockIdx.x * QROWS;
    const int head = blockIdx.y;
    const int b    = head >> 4;
    const int grp  = (head >> 2) & 3;
    const int p    = head & 3;
    const int h    = grp * 4 + p;

    const float* Kbase = Kg + (size_t)(b * S_) * KV_ + grp * HD_;
    const float* Vbase = Vg + (size_t)(b * S_) * KV_ + grp * HD_;

    const int kc  = tid >> 4;            // row base; rows kc + 8i
    const int kdw = (tid & 15) * 2;      // K word col
    const int vd  = (tid & 15) * 4;      // V word col

    float4 kst[8];           // K staging
    float4 vsa[4], vsb[4];   // V staging (key rows 2kw, 2kw+1)

    auto ldg_tile = [&](int kv0) {
#pragma unroll
        for (int i = 0; i < 8; i++) {
            int c = kc + 8 * i;
            kst[i] = *(const float4*)(Kbase + (size_t)(kv0 + c) * KV_ + kdw * 2);
        }
#pragma unroll
        for (int i = 0; i < 4; i++) {
            int kw = kc + 8 * i;
            size_t base = (size_t)(kv0 + 2 * kw) * KV_ + vd;
            vsa[i] = *(const float4*)(Vbase + base);
            vsb[i] = *(const float4*)(Vbase + base + KV_);
        }
    };
    auto sts_tile = [&]() {
#pragma unroll
        for (int i = 0; i < 8; i++) {
            int c = kc + 8 * i;
            uint2 t;
            t.x = f2h2(kst[i].x, kst[i].y);
            t.y = f2h2(kst[i].z, kst[i].w);
            *(uint2*)&Ks[c][kdw] = t;
        }
#pragma unroll
        for (int i = 0; i < 4; i++) {
            int kw = kc + 8 * i;
            uint4 t;
            t.x = f2h2(vsa[i].x, vsb[i].x);
            t.y = f2h2(vsa[i].y, vsb[i].y);
            t.z = f2h2(vsa[i].z, vsb[i].z);
            t.w = f2h2(vsa[i].w, vsb[i].w);
            *(uint4*)&Vsp[kw][vd] = t;
        }
    };

    // Load Q tile (scaled, packed half2) + prefetch first K/V tile.
#pragma unroll
    for (int i = 0; i < 16; i++) {
        int idx = tid + NTHR * i;
        int r = idx >> 4;
        int dw = (idx & 15) * 2;
        float4 v = *(const float4*)(Qg + (size_t)(b * S_ + q0 + r) * E_ + h * HD_ + dw * 2);
        uint2 t;
        t.x = f2h2(v.x * QSCALE, v.y * QSCALE);
        t.y = f2h2(v.z * QSCALE, v.w * QSCALE);
        *(uint2*)&Qs[r][dw] = t;
    }
    ldg_tile(0);

    float oacc[2][8][4];
#pragma unroll
    for (int mt = 0; mt < 2; mt++)
#pragma unroll
        for (int nt = 0; nt < 8; nt++)
#pragma unroll
            for (int r = 0; r < 4; r++) oacc[mt][nt][r] = 0.0f;

    float lrow[2][2];
#pragma unroll
    for (int mt = 0; mt < 2; mt++) { lrow[mt][0] = 0.0f; lrow[mt][1] = 0.0f; }

    const int NTILE = S_ / 64;
    for (int t = 0; t < NTILE; t++) {
        __syncthreads();     // consumers of tile t-1 done with Ks/Vsp
        sts_tile();
        __syncthreads();     // tile t visible
        if (t + 1 < NTILE) ldg_tile((t + 1) * 64);   // hidden behind compute

        // ---- S = Q @ K^T : warp tile 32 x 64 (k = d, 4 steps of k16) ----
        float sacc[2][8][4];
#pragma unroll
        for (int mt = 0; mt < 2; mt++)
#pragma unroll
            for (int nt = 0; nt < 8; nt++)
#pragma unroll
                for (int r = 0; r < 4; r++) sacc[mt][nt][r] = 0.0f;

#pragma unroll
        for (int ks = 0; ks < 4; ks++) {
            unsigned a[2][4];
#pragma unroll
            for (int mt = 0; mt < 2; mt++) {
                int row = wq0 + mt * 16 + gid;
                a[mt][0] = Qs[row][ks * 8 + tg];
                a[mt][1] = Qs[row + 8][ks * 8 + tg];
                a[mt][2] = Qs[row][ks * 8 + tg + 4];
                a[mt][3] = Qs[row + 8][ks * 8 + tg + 4];
            }
            unsigned bb[8][2];
#pragma unroll
            for (int nt = 0; nt < 8; nt++) {
                bb[nt][0] = Ks[nt * 8 + gid][ks * 8 + tg];
                bb[nt][1] = Ks[nt * 8 + gid][ks * 8 + tg + 4];
            }
#pragma unroll
            for (int mt = 0; mt < 2; mt++)
#pragma unroll
                for (int nt = 0; nt < 8; nt++)
                    mma_f16(sacc[mt][nt], a[mt], bb[nt]);
        }

        // ---- fixed-shift softmax: e = exp2(s'); pack adjacent-key pairs ----
#pragma unroll
        for (int mt = 0; mt < 2; mt++) {
            int r1 = wq0 + mt * 16 + gid;
            float sum0 = lrow[mt][0], sum1 = lrow[mt][1];
#pragma unroll
            for (int nt = 0; nt < 8; nt++) {
                float e0 = exp2f(sacc[mt][nt][0]);
                float e1 = exp2f(sacc[mt][nt][1]);
                float e2 = exp2f(sacc[mt][nt][2]);
                float e3 = exp2f(sacc[mt][nt][3]);
                sum0 += e0 + e1;
                sum1 += e2 + e3;
                Ps[r1][nt * 4 + tg]     = f2h2(e0, e1);
                Ps[r1 + 8][nt * 4 + tg] = f2h2(e2, e3);
            }
            lrow[mt][0] = sum0;
            lrow[mt][1] = sum1;
        }

        __syncwarp();   // Ps rows are warp-private

        // ---- O += P @ V : warp tile 32 x 64 (k = key, 4 steps of k16) ----
#pragma unroll
        for (int ks = 0; ks < 4; ks++) {
            unsigned a[2][4];
#pragma unroll
            for (int mt = 0; mt < 2; mt++) {
                int row = wq0 + mt * 16 + gid;
                a[mt][0] = Ps[row][ks * 8 + tg];
                a[mt][1] = Ps[row + 8][ks * 8 + tg];
                a[mt][2] = Ps[row][ks * 8 + tg + 4];
                a[mt][3] = Ps[row + 8][ks * 8 + tg + 4];
            }
            unsigned bb[8][2];
#pragma unroll
            for (int nt = 0; nt < 8; nt++) {
                bb[nt][0] = Vsp[ks * 8 + tg][nt * 8 + gid];
                bb[nt][1] = Vsp[ks * 8 + tg + 4][nt * 8 + gid];
            }
#pragma unroll
            for (int mt = 0; mt < 2; mt++)
#pragma unroll
                for (int nt = 0; nt < 8; nt++)
                    mma_f16(oacc[mt][nt], a[mt], bb[nt]);
        }
    }

    // Deferred row-sum reduction (4 lanes per row share the sum).
#pragma unroll
    for (int mt = 0; mt < 2; mt++) {
#pragma unroll
        for (int j = 0; j < 2; j++) {
            lrow[mt][j] += __shfl_xor_sync(0xffffffffu, lrow[mt][j], 1);
            lrow[mt][j] += __shfl_xor_sync(0xffffffffu, lrow[mt][j], 2);
        }
    }

    // Normalize + store permuted: col = p*256 + grp*64 + d
    const int cbase = p * (G_ * HD_) + grp * HD_;
#pragma unroll
    for (int mt = 0; mt < 2; mt++) {
        float inv0 = 1.0f / lrow[mt][0];
        float inv1 = 1.0f / lrow[mt][1];
        int r0 = b * S_ + q0 + wq0 + mt * 16 + gid;
#pragma unroll
        for (int nt = 0; nt < 8; nt++) {
            int c = cbase + nt * 8 + 2 * tg;
            float2 v0 = make_float2(oacc[mt][nt][0] * inv0, oacc[mt][nt][1] * inv0);
            float2 v1 = make_float2(oacc[mt][nt][2] * inv1, oacc[mt][nt][3] * inv1);
            *(float2*)&Ag[(size_t)r0 * E_ + c]       = v0;
            *(float2*)&Ag[(size_t)(r0 + 8) * E_ + c] = v1;
        }
    }
}

// ---------------------------------------------------------------------------
// Launch
// ---------------------------------------------------------------------------
extern "C" void kernel_launch(void* const* d_in, const int* in_sizes, int n_in,
                              void* d_out, int out_size)
{
    const float* x  = (const float*)d_in[0];
    const float* Wq = (const float*)d_in[1];
    const float* bq = (const float*)d_in[2];
    const float* Wk = (const float*)d_in[3];
    const float* bk = (const float*)d_in[4];
    const float* Wv = (const float*)d_in[5];
    const float* bv = (const float*)d_in[6];
    const float* Wo = (const float*)d_in[7];
    const float* bo = (const float*)d_in[8];
    float* out = (float*)d_out;

    float *Qp, *Kp, *Vp, *Ap;
    cudaGetSymbolAddress((void**)&Qp, g_Q);
    cudaGetSymbolAddress((void**)&Kp, g_K);
    cudaGetSymbolAddress((void**)&Vp, g_V);
    cudaGetSymbolAddress((void**)&Ap, g_A);

    const int smem_attn =
        (QROWS * QSTR + 64 * KSTR + 32 * VSTR + QROWS * QSTR) * (int)sizeof(unsigned); // 55296
    cudaFuncSetAttribute((const void*)attn_f16,
                         cudaFuncAttributeMaxDynamicSharedMemorySize, smem_attn);

    // Q projection (block tile 128x256)
    gemm_f16<<<dim3(E_ / 256, M_ / 128), 256>>>(x, Wq, bq, Qp, M_, E_, E_);
    // K + V projections fused
    gemm_kv_f16<<<dim3(2, M_ / 128), 256>>>(x, Wk, bk, Kp, Wv, bv, Vp);
    // Attention (permuted output)
    attn_f16<<<dim3(S_ / QROWS, B_ * 16), NTHR, smem_attn>>>(Qp, Kp, Vp, Ap);
    // Output projection
    gemm_f16<<<dim3(E_ / 256, M_ / 128), 256>>>(Ap, Wo, bo, out, M_, E_, E_);
}